// round 14
// baseline (speedup 1.0000x reference)
#include <cuda_runtime.h>
#include <cstdint>

#define N32   32
#define M64   64
#define BSZ   512
#define ALPHA 1.0f
#define BETA  1.0f

__device__ int gItersDefault = 1000;

// Dynamic smem layout (floats):
//   ring [0:8448)      16 slots x 4 rows x 132
//   Dm   [8448:12544)  D (64x64)
//   Ht   [12544:14592) Hinv tiles: Ht[m*128 + lane*4 + e] = Hinv[lane][4m+e]
// Preproc aliases inside ring region: w0 @0 (2048), w1 @2048 (1024), w2 @3072 (2048, E), sH @5120 (2048)
#define SMEM_FLOATS 14592
#define SMEM_BYTES  (SMEM_FLOATS * 4)

// ----------------------------- helpers -----------------------------
__device__ __forceinline__ unsigned long long ffma2(unsigned long long a,
                                                    unsigned long long b,
                                                    unsigned long long c) {
    unsigned long long d;
    asm("fma.rn.f32x2 %0, %1, %2, %3;" : "=l"(d) : "l"(a), "l"(b), "l"(c));
    return d;
}
__device__ __forceinline__ unsigned long long add2(unsigned long long a,
                                                   unsigned long long b) {
    unsigned long long d;
    asm("add.rn.f32x2 %0, %1, %2;" : "=l"(d) : "l"(a), "l"(b));
    return d;
}
__device__ __forceinline__ float hsum2(unsigned long long a) {
    float lo, hi;
    asm("mov.b64 {%0, %1}, %2;" : "=f"(lo), "=f"(hi) : "l"(a));
    return lo + hi;
}
// compiler-only ordering fence (branch-free converged warp; no WARPSYNC emitted)
__device__ __forceinline__ void cfence() { asm volatile("" ::: "memory"); }

__device__ __forceinline__ float warpMax(float v) {
#pragma unroll
    for (int o = 16; o; o >>= 1) v = fmaxf(v, __shfl_xor_sync(0xffffffffu, v, o));
    return v;
}
__device__ __forceinline__ float warpSum(float v) {
#pragma unroll
    for (int o = 16; o; o >>= 1) v += __shfl_xor_sync(0xffffffffu, v, o);
    return v;
}

// ----------------------------- producer: 2 rows interleaved, one 8-iter block -----------------------------
template<int S0>
__device__ __forceinline__ void produce8x2(
    float* __restrict__ ringA, float* __restrict__ ringB, int l,
    const unsigned long long* __restrict__ d0,
    const unsigned long long* __restrict__ d1,
    float tf, float a2t, float c22,
    float2 muA, float2 bA, float2 muB, float2 bB,
    float2& x1A, float2& x2A, float2& x1B, float2& x2B)
{
#pragma unroll
    for (int j = 0; j < 8; ++j) {
        const float* XrA = ringA + (S0 + j) * 528;
        const float* XrB = ringB + (S0 + j) * 528;
        unsigned long long aA0 = 0ull, aA1 = 0ull, aA2 = 0ull, aA3 = 0ull;
        unsigned long long aB0 = 0ull, aB1 = 0ull, aB2 = 0ull, aB3 = 0ull;
#pragma unroll
        for (int q4 = 0; q4 < 16; ++q4) {
            ulonglong2 xvA = *reinterpret_cast<const ulonglong2*>(XrA + 4 * q4);
            ulonglong2 xvB = *reinterpret_cast<const ulonglong2*>(XrB + 4 * q4);
            aA0 = ffma2(d0[2 * q4],     xvA.x, aA0);
            aB0 = ffma2(d0[2 * q4],     xvB.x, aB0);
            aA1 = ffma2(d0[2 * q4 + 1], xvA.y, aA1);
            aB1 = ffma2(d0[2 * q4 + 1], xvB.y, aB1);
            aA2 = ffma2(d1[2 * q4],     xvA.x, aA2);
            aB2 = ffma2(d1[2 * q4],     xvB.x, aB2);
            aA3 = ffma2(d1[2 * q4 + 1], xvA.y, aA3);
            aB3 = ffma2(d1[2 * q4 + 1], xvB.y, aB3);
        }
        float w0A = hsum2(add2(aA0, aA1));
        float w1A = hsum2(add2(aA2, aA3));
        float w0B = hsum2(add2(aB0, aB1));
        float w1B = hsum2(add2(aB2, aB3));

        float2 m1A, m2A, m1B, m2B;
        m1A.x = fmaf(tf, w0A + x2A.x, muA.x);
        m1A.y = fmaf(tf, w1A + x2A.y, muA.y);
        m2A.x = fmaxf(fmaf(-a2t, w0A, fmaf(c22, x2A.x, x1A.x)) + bA.x, 0.0f);
        m2A.y = fmaxf(fmaf(-a2t, w1A, fmaf(c22, x2A.y, x1A.y)) + bA.y, 0.0f);
        m1B.x = fmaf(tf, w0B + x2B.x, muB.x);
        m1B.y = fmaf(tf, w1B + x2B.y, muB.y);
        m2B.x = fmaxf(fmaf(-a2t, w0B, fmaf(c22, x2B.x, x1B.x)) + bB.x, 0.0f);
        m2B.y = fmaxf(fmaf(-a2t, w1B, fmaf(c22, x2B.y, x1B.y)) + bB.y, 0.0f);
        x1A = m1A; x2A = m2A; x1B = m1B; x2B = m2B;

        float* XwA = ringA + ((S0 + j + 1) & 15) * 528;
        float* XwB = ringB + ((S0 + j + 1) & 15) * 528;
        *reinterpret_cast<float2*>(XwA + 2 * l)      = m1A;
        *reinterpret_cast<float2*>(XwA + 64 + 2 * l) = m2A;
        *reinterpret_cast<float2*>(XwB + 2 * l)      = m1B;
        *reinterpret_cast<float2*>(XwB + 64 + 2 * l) = m2B;
        cfence();
    }
}

// runtime-slot tail (iters % 8 != 0 only)
__device__ __forceinline__ void produce_tail2(
    float* __restrict__ ringA, float* __restrict__ ringB, int l,
    const unsigned long long* __restrict__ d0,
    const unsigned long long* __restrict__ d1,
    float tf, float a2t, float c22,
    float2 muA, float2 bA, float2 muB, float2 bB,
    float2& x1A, float2& x2A, float2& x1B, float2& x2B,
    int kb, int nk)
{
    for (int j = 0; j < nk; ++j) {
        int k = kb + j;
        const float* XrA = ringA + ((k - 1) & 15) * 528;
        const float* XrB = ringB + ((k - 1) & 15) * 528;
        unsigned long long aA0 = 0ull, aA1 = 0ull, aA2 = 0ull, aA3 = 0ull;
        unsigned long long aB0 = 0ull, aB1 = 0ull, aB2 = 0ull, aB3 = 0ull;
#pragma unroll
        for (int q4 = 0; q4 < 16; ++q4) {
            ulonglong2 xvA = *reinterpret_cast<const ulonglong2*>(XrA + 4 * q4);
            ulonglong2 xvB = *reinterpret_cast<const ulonglong2*>(XrB + 4 * q4);
            aA0 = ffma2(d0[2 * q4],     xvA.x, aA0);
            aB0 = ffma2(d0[2 * q4],     xvB.x, aB0);
            aA1 = ffma2(d0[2 * q4 + 1], xvA.y, aA1);
            aB1 = ffma2(d0[2 * q4 + 1], xvB.y, aB1);
            aA2 = ffma2(d1[2 * q4],     xvA.x, aA2);
            aB2 = ffma2(d1[2 * q4],     xvB.x, aB2);
            aA3 = ffma2(d1[2 * q4 + 1], xvA.y, aA3);
            aB3 = ffma2(d1[2 * q4 + 1], xvB.y, aB3);
        }
        float w0A = hsum2(add2(aA0, aA1));
        float w1A = hsum2(add2(aA2, aA3));
        float w0B = hsum2(add2(aB0, aB1));
        float w1B = hsum2(add2(aB2, aB3));
        float2 m1A, m2A, m1B, m2B;
        m1A.x = fmaf(tf, w0A + x2A.x, muA.x);
        m1A.y = fmaf(tf, w1A + x2A.y, muA.y);
        m2A.x = fmaxf(fmaf(-a2t, w0A, fmaf(c22, x2A.x, x1A.x)) + bA.x, 0.0f);
        m2A.y = fmaxf(fmaf(-a2t, w1A, fmaf(c22, x2A.y, x1A.y)) + bA.y, 0.0f);
        m1B.x = fmaf(tf, w0B + x2B.x, muB.x);
        m1B.y = fmaf(tf, w1B + x2B.y, muB.y);
        m2B.x = fmaxf(fmaf(-a2t, w0B, fmaf(c22, x2B.x, x1B.x)) + bB.x, 0.0f);
        m2B.y = fmaxf(fmaf(-a2t, w1B, fmaf(c22, x2B.y, x1B.y)) + bB.y, 0.0f);
        x1A = m1A; x2A = m2A; x1B = m1B; x2B = m2B;
        float* XwA = ringA + (k & 15) * 528;
        float* XwB = ringB + (k & 15) * 528;
        *reinterpret_cast<float2*>(XwA + 2 * l)      = m1A;
        *reinterpret_cast<float2*>(XwA + 64 + 2 * l) = m2A;
        *reinterpret_cast<float2*>(XwB + 2 * l)      = m1B;
        *reinterpret_cast<float2*>(XwB + 64 + 2 * l) = m2B;
        cfence();
    }
}

// consumer: primal + gmem stores for 2 rows, nk iterations starting at kb
__device__ __forceinline__ void consume_block2(
    const float* __restrict__ ringA, const float* __restrict__ ringB, int l,
    const unsigned long long* __restrict__ hreg, float clA, float clB,
    float* __restrict__ xoA, float* __restrict__ poA,
    float* __restrict__ xoB, float* __restrict__ poB,
    int kb, int nk)
{
    for (int j = 0; j < nk; ++j) {
        int k = kb + j;
        const float* xa = ringA + (k & 15) * 528;
        const float* xb = ringB + (k & 15) * 528;
        unsigned long long pA0 = 0ull, pA1 = 0ull, pB0 = 0ull, pB1 = 0ull;
#pragma unroll
        for (int m = 0; m < 8; ++m) {
            ulonglong2 a0 = *reinterpret_cast<const ulonglong2*>(xa + 64 + 8 * m);
            ulonglong2 a1 = *reinterpret_cast<const ulonglong2*>(xa + 64 + 8 * m + 4);
            ulonglong2 b0 = *reinterpret_cast<const ulonglong2*>(xb + 64 + 8 * m);
            ulonglong2 b1 = *reinterpret_cast<const ulonglong2*>(xb + 64 + 8 * m + 4);
            pA0 = ffma2(hreg[4 * m],     a0.x, pA0);
            pB0 = ffma2(hreg[4 * m],     b0.x, pB0);
            pA1 = ffma2(hreg[4 * m + 1], a0.y, pA1);
            pB1 = ffma2(hreg[4 * m + 1], b0.y, pB1);
            pA0 = ffma2(hreg[4 * m + 2], a1.x, pA0);
            pB0 = ffma2(hreg[4 * m + 2], b1.x, pB0);
            pA1 = ffma2(hreg[4 * m + 3], a1.y, pA1);
            pB1 = ffma2(hreg[4 * m + 3], b1.y, pB1);
        }
        float pvA = hsum2(add2(pA0, pA1)) - clA;
        float pvB = hsum2(add2(pB0, pB1)) - clB;
        float4 vA = *reinterpret_cast<const float4*>(xa + 4 * l);
        float4 vB = *reinterpret_cast<const float4*>(xb + 4 * l);
        __stcs(reinterpret_cast<float4*>(xoA + (size_t)k * 128 + 4 * l), vA);
        __stcs(reinterpret_cast<float4*>(xoB + (size_t)k * 128 + 4 * l), vB);
        __stcs(poA + (size_t)k * 32 + l, pvA);
        __stcs(poB + (size_t)k * 32 + l, pvB);
    }
}

__global__ void __launch_bounds__(256, 1)
qp_kernel(const int* __restrict__ itp,
          const float* __restrict__ q, const float* __restrict__ bb,
          const float* __restrict__ P, const float* __restrict__ Hg,
          float* __restrict__ out) {
    extern __shared__ __align__(16) float smem[];
    __shared__ float sred8[8];
    __shared__ float sy[64], sz[64];
    __shared__ float sTf;
    __shared__ int sidx;

    float* ring = smem;
    float* Dm   = smem + 8448;
    float* Ht   = smem + 12544;
    float* w0 = ring;
    float* w1 = ring + 2048;
    float* w2 = ring + 3072;
    float* sH = ring + 5120;

    const int tid = threadIdx.x;
    const int wid = tid >> 5;
    const int l   = tid & 31;

    for (int i = tid; i < 2048; i += 256) sH[i] = Hg[i];

    // ================= PHASE 1: preprocessing (256 threads) =================
    for (int i = tid; i < 2048; i += 256) {
        int r = i >> 6, c = i & 63;
        w0[i] = (c < 32) ? P[r * 32 + c] : ((c - 32 == r) ? 1.0f : 0.0f);
    }
    __syncthreads();
    for (int p = 0; p < 32; ++p) {
        float pv = w0[p * 64 + p];
        float ipv = 1.0f / pv;
        __syncthreads();
        if (tid < 64) w0[p * 64 + tid] *= ipv;
        __syncthreads();
        int rr = tid >> 3, cs = (tid & 7) * 8;
        float f = w0[rr * 64 + p];
        __syncthreads();
        if (rr != p) {
#pragma unroll
            for (int c = 0; c < 8; ++c)
                w0[rr * 64 + cs + c] = fmaf(-f, w0[p * 64 + cs + c], w0[rr * 64 + cs + c]);
        }
        __syncthreads();
    }
    for (int i = tid; i < 1024; i += 256) w1[i] = w0[(i >> 5) * 64 + 32 + (i & 31)];
    __syncthreads();

    for (int i = tid; i < 2048; i += 256) {
        int r = i >> 6, c = i & 63;
        float s = 0.0f;
#pragma unroll 8
        for (int k = 0; k < 32; ++k) s = fmaf(w1[r * 32 + k], sH[c * 32 + k], s);
        w2[i] = s;
    }
    __syncthreads();

    for (int i = tid; i < 4096; i += 256) {
        int a = i >> 6, c = i & 63;
        float s0 = 0.0f, s1 = 0.0f;
        for (int k = 0; k < 32; k += 2) {
            s0 = fmaf(sH[a * 32 + k],     w2[k * 64 + c],       s0);
            s1 = fmaf(sH[a * 32 + k + 1], w2[(k + 1) * 64 + c], s1);
        }
        Dm[i] = s0 + s1;
    }
    for (int i = tid; i < 1024; i += 256) {
        int r = i >> 5, c = i & 31;
        float s0 = 0.0f, s1 = 0.0f;
        for (int m = 0; m < 64; m += 2) {
            s0 = fmaf(w2[r * 64 + m],     sH[m * 32 + c],       s0);
            s1 = fmaf(w2[r * 64 + m + 1], sH[(m + 1) * 32 + c], s1);
        }
        w0[i] = s0 + s1;
    }
    __syncthreads();

    {
        float loc = 0.0f;
        for (int i = tid; i < 1024; i += 256) loc = fmaxf(loc, fabsf(w0[i]));
        loc = warpMax(loc);
        if (l == 0) sred8[wid] = loc;
        __syncthreads();
        float m = 0.0f;
#pragma unroll
        for (int j = 0; j < 8; ++j) m = fmaxf(m, sred8[j]);
        float inv = 1.0f / m;
        for (int i = tid; i < 1024; i += 256) w0[i] *= inv;
        __syncthreads();
    }
    {
        const int r4 = tid >> 3, c4 = (tid & 7) << 2;
        float* cur = w0;
        float* nxt = w0 + 1024;
        for (int s = 0; s < 13; ++s) {
            float acc[4] = {0, 0, 0, 0};
            for (int k = 0; k < 32; ++k) {
                float a = cur[r4 * 32 + k];
#pragma unroll
                for (int j = 0; j < 4; ++j)
                    acc[j] = fmaf(a, cur[k * 32 + c4 + j], acc[j]);
            }
            float loc = fmaxf(fmaxf(fabsf(acc[0]), fabsf(acc[1])),
                              fmaxf(fabsf(acc[2]), fabsf(acc[3])));
            loc = warpMax(loc);
            if (l == 0) sred8[wid] = loc;
            __syncthreads();
            float m = 0.0f;
#pragma unroll
            for (int j = 0; j < 8; ++j) m = fmaxf(m, sred8[j]);
            float inv = 1.0f / m;
#pragma unroll
            for (int j = 0; j < 4; ++j) nxt[r4 * 32 + c4 + j] = acc[j] * inv;
            __syncthreads();
            float* t = cur; cur = nxt; nxt = t;
        }
        if (tid < 32) {
            float s = 0.0f;
            for (int i = 0; i < 32; ++i) { float v = cur[i * 32 + tid]; s = fmaf(v, v, s); }
            sy[tid] = s;
        }
        __syncthreads();
        if (tid == 0) {
            int bj = 0; float bm = -1.0f;
            for (int j = 0; j < 32; ++j) if (sy[j] > bm) { bm = sy[j]; bj = j; }
            sidx = bj;
        }
        __syncthreads();
        if (tid < 64) {
            float s = 0.0f;
            for (int i = 0; i < 32; ++i) s = fmaf(sH[tid * 32 + i], cur[i * 32 + sidx], s);
            sy[tid] = s;
        }
        __syncthreads();
        if (tid < 64) {
            float s = 0.0f;
            for (int k = 0; k < 64; ++k) s = fmaf(Dm[tid * 64 + k], sy[k], s);
            sz[tid] = s;
        }
        __syncthreads();
        float p1 = (tid < 64) ? sy[tid] * sz[tid] : 0.0f;
        float p2 = (tid < 64) ? sy[tid] * sy[tid] : 0.0f;
        p1 = warpSum(p1);
        p2 = warpSum(p2);
        __syncthreads();
        if (l == 0) { sy[wid] = p1; sz[wid] = p2; }
        __syncthreads();
        if (tid == 0) {
            float num = 0.0f, den = 0.0f;
#pragma unroll
            for (int j = 0; j < 8; ++j) { num += sy[j]; den += sz[j]; }
            sTf = BETA * den / num;
        }
    }
    __syncthreads();

    for (int i = tid; i < 2048; i += 256) {
        int r = i >> 6, c = i & 63;
        if (c < 32) {
            float s0 = 0.0f, s1 = 0.0f;
            for (int m = 0; m < 64; m += 2) {
                s0 = fmaf(sH[m * 32 + r],       sH[m * 32 + c],       s0);
                s1 = fmaf(sH[(m + 1) * 32 + r], sH[(m + 1) * 32 + c], s1);
            }
            w0[i] = s0 + s1;
        } else {
            w0[i] = (c - 32 == r) ? 1.0f : 0.0f;
        }
    }
    __syncthreads();
    for (int p = 0; p < 32; ++p) {
        float pv = w0[p * 64 + p];
        float ipv = 1.0f / pv;
        __syncthreads();
        if (tid < 64) w0[p * 64 + tid] *= ipv;
        __syncthreads();
        int rr = tid >> 3, cs = (tid & 7) * 8;
        float f = w0[rr * 64 + p];
        __syncthreads();
        if (rr != p) {
#pragma unroll
            for (int c = 0; c < 8; ++c)
                w0[rr * 64 + cs + c] = fmaf(-f, w0[p * 64 + cs + c], w0[rr * 64 + cs + c]);
        }
        __syncthreads();
    }
    for (int i = tid; i < 1024; i += 256) w1[i] = w0[(i >> 5) * 64 + 32 + (i & 31)];
    __syncthreads();

    for (int i = tid; i < 2048; i += 256) {
        int r = i >> 6, c = i & 63;
        float s = 0.0f;
#pragma unroll 8
        for (int k = 0; k < 32; ++k) s = fmaf(w1[r * 32 + k], sH[c * 32 + k], s);
        Ht[(c >> 2) * 128 + r * 4 + (c & 3)] = s;
    }
    __syncthreads();

    // warps 4-7 retire; phase 2 runs on 4 warps (1 per SMSP)
    if (wid >= 4) return;

    // ================= PHASE 2 =================
    // wid 0,1: producers, 2 rows each (shared D registers, interleaved chains)
    // wid 2,3: consumers, 2 rows each
    const int iters = *itp;
    const size_t K = (size_t)iters + 1;
    const int nfull = iters >> 3;
    const int rem = iters & 7;

    if (wid < 2) {
        // -------- PRODUCER: local rows 2*wid, 2*wid+1 --------
        const int lr0 = 2 * wid;
        const int rA = blockIdx.x * 4 + lr0;
        const int rB = rA + 1;
        float* ringA = ring + lr0 * 132;
        float* ringB = ring + (lr0 + 1) * 132;

        unsigned long long d0[32], d1[32];
#pragma unroll
        for (int kk = 0; kk < 32; ++kk) {
            d0[kk] = *reinterpret_cast<const unsigned long long*>(&Dm[(2 * l)     * 64 + 2 * kk]);
            d1[kk] = *reinterpret_cast<const unsigned long long*>(&Dm[(2 * l + 1) * 64 + 2 * kk]);
        }

        const float tf  = sTf;
        const float a2t = 2.0f * ALPHA * tf;
        const float c22 = 1.0f - a2t;

        float2 muA, muB;
        {
            float sA0 = 0.0f, sA1 = 0.0f, sB0 = 0.0f, sB1 = 0.0f;
#pragma unroll 8
            for (int i = 0; i < 32; ++i) {
                float qa = q[rA * 32 + i];
                float qb = q[rB * 32 + i];
                float2 ev = *reinterpret_cast<const float2*>(&w2[i * 64 + 2 * l]);
                sA0 = fmaf(qa, ev.x, sA0);
                sA1 = fmaf(qa, ev.y, sA1);
                sB0 = fmaf(qb, ev.x, sB0);
                sB1 = fmaf(qb, ev.y, sB1);
            }
            float2 bvA = *reinterpret_cast<const float2*>(&bb[rA * 64 + 2 * l]);
            float2 bvB = *reinterpret_cast<const float2*>(&bb[rB * 64 + 2 * l]);
            muA.x = tf * (sA0 - bvA.x);
            muA.y = tf * (sA1 - bvA.y);
            muB.x = tf * (sB0 - bvB.x);
            muB.y = tf * (sB1 - bvB.y);
        }
        const float2 bA = make_float2(-2.0f * ALPHA * muA.x, -2.0f * ALPHA * muA.y);
        const float2 bB = make_float2(-2.0f * ALPHA * muB.x, -2.0f * ALPHA * muB.y);

        *reinterpret_cast<float4*>(ringA + 4 * l) = make_float4(0.f, 0.f, 0.f, 0.f);
        *reinterpret_cast<float4*>(ringB + 4 * l) = make_float4(0.f, 0.f, 0.f, 0.f);
        float2 x1A = make_float2(0.f, 0.f), x2A = make_float2(0.f, 0.f);
        float2 x1B = make_float2(0.f, 0.f), x2B = make_float2(0.f, 0.f);
        __syncthreads();   // prologue barrier (4 warps)

        for (int B = 0; B <= nfull; ++B) {
            if (B < nfull) {
                if (B & 1)
                    produce8x2<8>(ringA, ringB, l, d0, d1, tf, a2t, c22,
                                  muA, bA, muB, bB, x1A, x2A, x1B, x2B);
                else
                    produce8x2<0>(ringA, ringB, l, d0, d1, tf, a2t, c22,
                                  muA, bA, muB, bB, x1A, x2A, x1B, x2B);
            } else if (rem) {
                produce_tail2(ringA, ringB, l, d0, d1, tf, a2t, c22,
                              muA, bA, muB, bB, x1A, x2A, x1B, x2B,
                              8 * nfull + 1, rem);
            }
            __syncthreads();
        }
    } else {
        // -------- CONSUMER: local rows 2*(wid-2), 2*(wid-2)+1 --------
        const int lr0 = 2 * (wid - 2);
        const int rA = blockIdx.x * 4 + lr0;
        const int rB = rA + 1;
        const float* ringA = ring + lr0 * 132;
        const float* ringB = ring + (lr0 + 1) * 132;

        unsigned long long hreg[32];
#pragma unroll
        for (int m = 0; m < 16; ++m) {
            ulonglong2 hv = *reinterpret_cast<const ulonglong2*>(&Ht[m * 128 + 4 * l]);
            hreg[2 * m]     = hv.x;
            hreg[2 * m + 1] = hv.y;
        }

        float clA, clB;
        {
            unsigned long long cA0 = 0ull, cA1 = 0ull, cB0 = 0ull, cB1 = 0ull;
#pragma unroll
            for (int m = 0; m < 8; ++m) {
                ulonglong2 a0 = *reinterpret_cast<const ulonglong2*>(&bb[rA * 64 + 8 * m]);
                ulonglong2 a1 = *reinterpret_cast<const ulonglong2*>(&bb[rA * 64 + 8 * m + 4]);
                ulonglong2 b0 = *reinterpret_cast<const ulonglong2*>(&bb[rB * 64 + 8 * m]);
                ulonglong2 b1 = *reinterpret_cast<const ulonglong2*>(&bb[rB * 64 + 8 * m + 4]);
                cA0 = ffma2(hreg[4 * m],     a0.x, cA0);
                cA1 = ffma2(hreg[4 * m + 1], a0.y, cA1);
                cA0 = ffma2(hreg[4 * m + 2], a1.x, cA0);
                cA1 = ffma2(hreg[4 * m + 3], a1.y, cA1);
                cB0 = ffma2(hreg[4 * m],     b0.x, cB0);
                cB1 = ffma2(hreg[4 * m + 1], b0.y, cB1);
                cB0 = ffma2(hreg[4 * m + 2], b1.x, cB0);
                cB1 = ffma2(hreg[4 * m + 3], b1.y, cB1);
            }
            clA = hsum2(add2(cA0, cA1));
            clB = hsum2(add2(cB0, cB1));
        }

        float* xoA = out + (size_t)rA * K * 128;
        float* poA = out + (size_t)BSZ * K * 128 + (size_t)rA * K * 32;
        float* xoB = out + (size_t)rB * K * 128;
        float* poB = out + (size_t)BSZ * K * 128 + (size_t)rB * K * 32;

        __stcs(reinterpret_cast<float4*>(&xoA[4 * l]), make_float4(0.f, 0.f, 0.f, 0.f));
        __stcs(reinterpret_cast<float4*>(&xoB[4 * l]), make_float4(0.f, 0.f, 0.f, 0.f));
        __stcs(&poA[l], -clA);
        __stcs(&poB[l], -clB);
        __syncthreads();   // prologue barrier

        for (int B = 0; B <= nfull; ++B) {
            if (B > 0)
                consume_block2(ringA, ringB, l, hreg, clA, clB,
                               xoA, poA, xoB, poB, 8 * (B - 1) + 1, 8);
            __syncthreads();
        }
        if (rem)
            consume_block2(ringA, ringB, l, hreg, clA, clB,
                           xoA, poA, xoB, poB, 8 * nfull + 1, rem);
    }
}

// ----------------------------- launch -----------------------------
extern "C" void kernel_launch(void* const* d_in, const int* in_sizes, int n_in,
                              void* d_out, int out_size) {
    (void)in_sizes; (void)out_size;
    const float* q = (const float*)d_in[0];
    const float* b = (const float*)d_in[1];
    const float* P = (const float*)d_in[2];
    const float* H = (const float*)d_in[3];

    const int* itp;
    if (n_in >= 5) {
        itp = (const int*)d_in[4];
    } else {
        void* p = nullptr;
        cudaGetSymbolAddress(&p, gItersDefault);
        itp = (const int*)p;
    }
    float* out = (float*)d_out;

    static bool attr_set = false;
    if (!attr_set) {
        cudaFuncSetAttribute(qp_kernel, cudaFuncAttributeMaxDynamicSharedMemorySize, SMEM_BYTES);
        attr_set = true;
    }
    qp_kernel<<<128, 256, SMEM_BYTES>>>(itp, q, b, P, H, out);
}

// round 15
// speedup vs baseline: 1.3280x; 1.3280x over previous
#include <cuda_runtime.h>
#include <cstdint>

#define N32   32
#define M64   64
#define BSZ   512
#define ALPHA 1.0f
#define BETA  1.0f

__device__ int gItersDefault = 1000;

// Dynamic smem layout (floats):
//   ring [0:8448)      16 slots x 4 rows x 132
//   Dm   [8448:12544)  D (64x64)
//   Ht   [12544:14592) Hinv tiles: Ht[m*128 + lane*4 + e] = Hinv[lane][4m+e]
// Preproc aliases inside ring region: w0 @0 (2048), w1 @2048 (1024), w2 @3072 (2048, E), sH @5120 (2048)
#define SMEM_FLOATS 14592
#define SMEM_BYTES  (SMEM_FLOATS * 4)

// ----------------------------- helpers -----------------------------
__device__ __forceinline__ unsigned long long ffma2(unsigned long long a,
                                                    unsigned long long b,
                                                    unsigned long long c) {
    unsigned long long d;
    asm("fma.rn.f32x2 %0, %1, %2, %3;" : "=l"(d) : "l"(a), "l"(b), "l"(c));
    return d;
}
__device__ __forceinline__ unsigned long long add2(unsigned long long a,
                                                   unsigned long long b) {
    unsigned long long d;
    asm("add.rn.f32x2 %0, %1, %2;" : "=l"(d) : "l"(a), "l"(b));
    return d;
}
__device__ __forceinline__ float hsum2(unsigned long long a) {
    float lo, hi;
    asm("mov.b64 {%0, %1}, %2;" : "=f"(lo), "=f"(hi) : "l"(a));
    return lo + hi;
}
__device__ __forceinline__ unsigned long long pack2(float lo, float hi) {
    unsigned long long d;
    asm("mov.b64 %0, {%1, %2};" : "=l"(d) : "f"(lo), "f"(hi));
    return d;
}
__device__ __forceinline__ float2 unpack2(unsigned long long a) {
    float2 r;
    asm("mov.b64 {%0, %1}, %2;" : "=f"(r.x), "=f"(r.y) : "l"(a));
    return r;
}
// compiler-only ordering fence (branch-free converged warp; no WARPSYNC emitted)
__device__ __forceinline__ void cfence() { asm volatile("" ::: "memory"); }

__device__ __forceinline__ float warpMax(float v) {
#pragma unroll
    for (int o = 16; o; o >>= 1) v = fmaxf(v, __shfl_xor_sync(0xffffffffu, v, o));
    return v;
}
__device__ __forceinline__ float warpSum(float v) {
#pragma unroll
    for (int o = 16; o; o >>= 1) v += __shfl_xor_sync(0xffffffffu, v, o);
    return v;
}

// ----------------------------- producer: one 8-iter block, compile-time slots -----------------------------
// Update identities (exact):
//   x1' = t*(w + x2) + mu
//   x2' = relu(x1 + x2 - 2*alpha*x1')
template<int S0>
__device__ __forceinline__ void produce8(
    float* __restrict__ ringW, int l,
    const unsigned long long* __restrict__ d0,
    const unsigned long long* __restrict__ d1,
    unsigned long long tf2, unsigned long long na2, unsigned long long mu22,
    float2& x1o, float2& x2o)
{
#pragma unroll
    for (int j = 0; j < 8; ++j) {
        const float* Xr = ringW + (S0 + j) * 528;
        unsigned long long a00 = 0ull, a01 = 0ull, a02 = 0ull, a03 = 0ull;
        unsigned long long a10 = 0ull, a11 = 0ull, a12 = 0ull, a13 = 0ull;
#pragma unroll
        for (int q4 = 0; q4 < 8; ++q4) {
            ulonglong2 xv = *reinterpret_cast<const ulonglong2*>(Xr + 4 * q4);
            a00 = ffma2(d0[2 * q4],     xv.x, a00);
            a01 = ffma2(d0[2 * q4 + 1], xv.y, a01);
            a10 = ffma2(d1[2 * q4],     xv.x, a10);
            a11 = ffma2(d1[2 * q4 + 1], xv.y, a11);
        }
#pragma unroll
        for (int q4 = 8; q4 < 16; ++q4) {
            ulonglong2 xv = *reinterpret_cast<const ulonglong2*>(Xr + 4 * q4);
            a02 = ffma2(d0[2 * q4],     xv.x, a02);
            a03 = ffma2(d0[2 * q4 + 1], xv.y, a03);
            a12 = ffma2(d1[2 * q4],     xv.x, a12);
            a13 = ffma2(d1[2 * q4 + 1], xv.y, a13);
        }
        float w0s = hsum2(add2(add2(a00, a01), add2(a02, a03)));
        float w1s = hsum2(add2(add2(a10, a11), add2(a12, a13)));
        unsigned long long w01 = pack2(w0s, w1s);
        unsigned long long x1p = pack2(x1o.x, x1o.y);
        unsigned long long x2p = pack2(x2o.x, x2o.y);

        // m1 = t*(w + x2) + mu   (packed)
        unsigned long long m1p = ffma2(tf2, add2(w01, x2p), mu22);
        // m2 = relu(x1 + x2 - 2a*m1)  (packed fma, scalar relu)
        unsigned long long s12 = add2(x1p, x2p);
        unsigned long long m2p = ffma2(na2, m1p, s12);
        float2 m1 = unpack2(m1p);
        float2 m2r = unpack2(m2p);
        float2 m2;
        m2.x = fmaxf(m2r.x, 0.0f);
        m2.y = fmaxf(m2r.y, 0.0f);
        x1o = m1; x2o = m2;

        float* Xw = ringW + ((S0 + j + 1) & 15) * 528;
        *reinterpret_cast<float2*>(Xw + 2 * l)      = m1;
        *reinterpret_cast<float2*>(Xw + 64 + 2 * l) = m2;
        cfence();
    }
}

// runtime-slot tail producer (iters % 8 != 0 only)
__device__ __forceinline__ void produce_tail(
    float* __restrict__ ringW, int l,
    const unsigned long long* __restrict__ d0,
    const unsigned long long* __restrict__ d1,
    unsigned long long tf2, unsigned long long na2, unsigned long long mu22,
    float2& x1o, float2& x2o, int kb, int nk)
{
    for (int j = 0; j < nk; ++j) {
        int k = kb + j;
        const float* Xr = ringW + ((k - 1) & 15) * 528;
        unsigned long long a00 = 0ull, a01 = 0ull, a10 = 0ull, a11 = 0ull;
#pragma unroll
        for (int q4 = 0; q4 < 16; ++q4) {
            ulonglong2 xv = *reinterpret_cast<const ulonglong2*>(Xr + 4 * q4);
            a00 = ffma2(d0[2 * q4],     xv.x, a00);
            a01 = ffma2(d0[2 * q4 + 1], xv.y, a01);
            a10 = ffma2(d1[2 * q4],     xv.x, a10);
            a11 = ffma2(d1[2 * q4 + 1], xv.y, a11);
        }
        float w0s = hsum2(add2(a00, a01));
        float w1s = hsum2(add2(a10, a11));
        unsigned long long w01 = pack2(w0s, w1s);
        unsigned long long x1p = pack2(x1o.x, x1o.y);
        unsigned long long x2p = pack2(x2o.x, x2o.y);
        unsigned long long m1p = ffma2(tf2, add2(w01, x2p), mu22);
        unsigned long long s12 = add2(x1p, x2p);
        unsigned long long m2p = ffma2(na2, m1p, s12);
        float2 m1 = unpack2(m1p);
        float2 m2r = unpack2(m2p);
        float2 m2;
        m2.x = fmaxf(m2r.x, 0.0f);
        m2.y = fmaxf(m2r.y, 0.0f);
        x1o = m1; x2o = m2;
        float* Xw = ringW + (k & 15) * 528;
        *reinterpret_cast<float2*>(Xw + 2 * l)      = m1;
        *reinterpret_cast<float2*>(Xw + 64 + 2 * l) = m2;
        cfence();
    }
}

// consumer: primal + gmem stores for nk iterations starting at kb
__device__ __forceinline__ void consume_block(
    const float* __restrict__ ringW, int l,
    const unsigned long long* __restrict__ hreg, float cl,
    float* __restrict__ xo, float* __restrict__ po,
    int kb, int nk)
{
    for (int j = 0; j < nk; ++j) {
        int k = kb + j;
        const float* xr = ringW + (k & 15) * 528;
        unsigned long long p0 = 0ull, p1 = 0ull, p2 = 0ull, p3 = 0ull;
#pragma unroll
        for (int m = 0; m < 8; ++m) {
            ulonglong2 x0 = *reinterpret_cast<const ulonglong2*>(xr + 64 + 8 * m);
            ulonglong2 x1 = *reinterpret_cast<const ulonglong2*>(xr + 64 + 8 * m + 4);
            p0 = ffma2(hreg[4 * m],     x0.x, p0);
            p1 = ffma2(hreg[4 * m + 1], x0.y, p1);
            p2 = ffma2(hreg[4 * m + 2], x1.x, p2);
            p3 = ffma2(hreg[4 * m + 3], x1.y, p3);
        }
        float pv = hsum2(add2(add2(p0, p1), add2(p2, p3))) - cl;
        float4 v = *reinterpret_cast<const float4*>(xr + 4 * l);
        __stcs(reinterpret_cast<float4*>(xo + (size_t)k * 128 + 4 * l), v);
        __stcs(po + (size_t)k * 32 + l, pv);
    }
}

__global__ void __launch_bounds__(256, 1)
qp_kernel(const int* __restrict__ itp,
          const float* __restrict__ q, const float* __restrict__ bb,
          const float* __restrict__ P, const float* __restrict__ Hg,
          float* __restrict__ out) {
    extern __shared__ __align__(16) float smem[];
    __shared__ float sred8[8];
    __shared__ float sy[64], sz[64];
    __shared__ float sTf;
    __shared__ int sidx;

    float* ring = smem;
    float* Dm   = smem + 8448;
    float* Ht   = smem + 12544;
    float* w0 = ring;
    float* w1 = ring + 2048;
    float* w2 = ring + 3072;
    float* sH = ring + 5120;

    const int tid = threadIdx.x;
    const int wid = tid >> 5;
    const int l   = tid & 31;

    for (int i = tid; i < 2048; i += 256) sH[i] = Hg[i];

    // ================= PHASE 1: preprocessing =================
    for (int i = tid; i < 2048; i += 256) {
        int r = i >> 6, c = i & 63;
        w0[i] = (c < 32) ? P[r * 32 + c] : ((c - 32 == r) ? 1.0f : 0.0f);
    }
    __syncthreads();
    for (int p = 0; p < 32; ++p) {
        float pv = w0[p * 64 + p];
        float ipv = 1.0f / pv;
        __syncthreads();
        if (tid < 64) w0[p * 64 + tid] *= ipv;
        __syncthreads();
        int rr = tid >> 3, cs = (tid & 7) * 8;
        float f = w0[rr * 64 + p];
        __syncthreads();
        if (rr != p) {
#pragma unroll
            for (int c = 0; c < 8; ++c)
                w0[rr * 64 + cs + c] = fmaf(-f, w0[p * 64 + cs + c], w0[rr * 64 + cs + c]);
        }
        __syncthreads();
    }
    for (int i = tid; i < 1024; i += 256) w1[i] = w0[(i >> 5) * 64 + 32 + (i & 31)];
    __syncthreads();

    for (int i = tid; i < 2048; i += 256) {
        int r = i >> 6, c = i & 63;
        float s = 0.0f;
#pragma unroll 8
        for (int k = 0; k < 32; ++k) s = fmaf(w1[r * 32 + k], sH[c * 32 + k], s);
        w2[i] = s;
    }
    __syncthreads();

    for (int i = tid; i < 4096; i += 256) {
        int a = i >> 6, c = i & 63;
        float s0 = 0.0f, s1 = 0.0f;
        for (int k = 0; k < 32; k += 2) {
            s0 = fmaf(sH[a * 32 + k],     w2[k * 64 + c],       s0);
            s1 = fmaf(sH[a * 32 + k + 1], w2[(k + 1) * 64 + c], s1);
        }
        Dm[i] = s0 + s1;
    }
    for (int i = tid; i < 1024; i += 256) {
        int r = i >> 5, c = i & 31;
        float s0 = 0.0f, s1 = 0.0f;
        for (int m = 0; m < 64; m += 2) {
            s0 = fmaf(w2[r * 64 + m],     sH[m * 32 + c],       s0);
            s1 = fmaf(w2[r * 64 + m + 1], sH[(m + 1) * 32 + c], s1);
        }
        w0[i] = s0 + s1;
    }
    __syncthreads();

    {
        float loc = 0.0f;
        for (int i = tid; i < 1024; i += 256) loc = fmaxf(loc, fabsf(w0[i]));
        loc = warpMax(loc);
        if (l == 0) sred8[wid] = loc;
        __syncthreads();
        float m = 0.0f;
#pragma unroll
        for (int j = 0; j < 8; ++j) m = fmaxf(m, sred8[j]);
        float inv = 1.0f / m;
        for (int i = tid; i < 1024; i += 256) w0[i] *= inv;
        __syncthreads();
    }
    {
        const int r4 = tid >> 3, c4 = (tid & 7) << 2;
        float* cur = w0;
        float* nxt = w0 + 1024;
        for (int s = 0; s < 13; ++s) {
            float acc[4] = {0, 0, 0, 0};
            for (int k = 0; k < 32; ++k) {
                float a = cur[r4 * 32 + k];
#pragma unroll
                for (int j = 0; j < 4; ++j)
                    acc[j] = fmaf(a, cur[k * 32 + c4 + j], acc[j]);
            }
            float loc = fmaxf(fmaxf(fabsf(acc[0]), fabsf(acc[1])),
                              fmaxf(fabsf(acc[2]), fabsf(acc[3])));
            loc = warpMax(loc);
            if (l == 0) sred8[wid] = loc;
            __syncthreads();
            float m = 0.0f;
#pragma unroll
            for (int j = 0; j < 8; ++j) m = fmaxf(m, sred8[j]);
            float inv = 1.0f / m;
#pragma unroll
            for (int j = 0; j < 4; ++j) nxt[r4 * 32 + c4 + j] = acc[j] * inv;
            __syncthreads();
            float* t = cur; cur = nxt; nxt = t;
        }
        if (tid < 32) {
            float s = 0.0f;
            for (int i = 0; i < 32; ++i) { float v = cur[i * 32 + tid]; s = fmaf(v, v, s); }
            sy[tid] = s;
        }
        __syncthreads();
        if (tid == 0) {
            int bj = 0; float bm = -1.0f;
            for (int j = 0; j < 32; ++j) if (sy[j] > bm) { bm = sy[j]; bj = j; }
            sidx = bj;
        }
        __syncthreads();
        if (tid < 64) {
            float s = 0.0f;
            for (int i = 0; i < 32; ++i) s = fmaf(sH[tid * 32 + i], cur[i * 32 + sidx], s);
            sy[tid] = s;
        }
        __syncthreads();
        if (tid < 64) {
            float s = 0.0f;
            for (int k = 0; k < 64; ++k) s = fmaf(Dm[tid * 64 + k], sy[k], s);
            sz[tid] = s;
        }
        __syncthreads();
        float p1 = (tid < 64) ? sy[tid] * sz[tid] : 0.0f;
        float p2 = (tid < 64) ? sy[tid] * sy[tid] : 0.0f;
        p1 = warpSum(p1);
        p2 = warpSum(p2);
        __syncthreads();
        if (l == 0) { sy[wid] = p1; sz[wid] = p2; }
        __syncthreads();
        if (tid == 0) {
            float num = 0.0f, den = 0.0f;
#pragma unroll
            for (int j = 0; j < 8; ++j) { num += sy[j]; den += sz[j]; }
            sTf = BETA * den / num;
        }
    }
    __syncthreads();

    for (int i = tid; i < 2048; i += 256) {
        int r = i >> 6, c = i & 63;
        if (c < 32) {
            float s0 = 0.0f, s1 = 0.0f;
            for (int m = 0; m < 64; m += 2) {
                s0 = fmaf(sH[m * 32 + r],       sH[m * 32 + c],       s0);
                s1 = fmaf(sH[(m + 1) * 32 + r], sH[(m + 1) * 32 + c], s1);
            }
            w0[i] = s0 + s1;
        } else {
            w0[i] = (c - 32 == r) ? 1.0f : 0.0f;
        }
    }
    __syncthreads();
    for (int p = 0; p < 32; ++p) {
        float pv = w0[p * 64 + p];
        float ipv = 1.0f / pv;
        __syncthreads();
        if (tid < 64) w0[p * 64 + tid] *= ipv;
        __syncthreads();
        int rr = tid >> 3, cs = (tid & 7) * 8;
        float f = w0[rr * 64 + p];
        __syncthreads();
        if (rr != p) {
#pragma unroll
            for (int c = 0; c < 8; ++c)
                w0[rr * 64 + cs + c] = fmaf(-f, w0[p * 64 + cs + c], w0[rr * 64 + cs + c]);
        }
        __syncthreads();
    }
    for (int i = tid; i < 1024; i += 256) w1[i] = w0[(i >> 5) * 64 + 32 + (i & 31)];
    __syncthreads();

    for (int i = tid; i < 2048; i += 256) {
        int r = i >> 6, c = i & 63;
        float s = 0.0f;
#pragma unroll 8
        for (int k = 0; k < 32; ++k) s = fmaf(w1[r * 32 + k], sH[c * 32 + k], s);
        Ht[(c >> 2) * 128 + r * 4 + (c & 3)] = s;
    }
    __syncthreads();

    // ================= PHASE 2: producer (wid<4) / consumer (wid>=4), 1 of each per SMSP =================
    const int iters = *itp;
    const size_t K = (size_t)iters + 1;
    const int nfull = iters >> 3;
    const int rem = iters & 7;

    if (wid < 4) {
        // -------- PRODUCER --------
        const int w = wid;
        const int r = blockIdx.x * 4 + w;
        float* ringW = ring + w * 132;

        unsigned long long d0[32], d1[32];
#pragma unroll
        for (int kk = 0; kk < 32; ++kk) {
            d0[kk] = *reinterpret_cast<const unsigned long long*>(&Dm[(2 * l)     * 64 + 2 * kk]);
            d1[kk] = *reinterpret_cast<const unsigned long long*>(&Dm[(2 * l + 1) * 64 + 2 * kk]);
        }

        const float tf = sTf;

        float2 mu2;
        {
            float s0 = 0.0f, s1 = 0.0f;
#pragma unroll 8
            for (int i = 0; i < 32; ++i) {
                float qi = q[r * 32 + i];
                float2 ev = *reinterpret_cast<const float2*>(&w2[i * 64 + 2 * l]);
                s0 = fmaf(qi, ev.x, s0);
                s1 = fmaf(qi, ev.y, s1);
            }
            float2 bv = *reinterpret_cast<const float2*>(&bb[r * 64 + 2 * l]);
            mu2.x = tf * (s0 - bv.x);
            mu2.y = tf * (s1 - bv.y);
        }
        const unsigned long long tf2  = pack2(tf, tf);
        const unsigned long long na2  = pack2(-2.0f * ALPHA, -2.0f * ALPHA);
        const unsigned long long mu22 = pack2(mu2.x, mu2.y);

        *reinterpret_cast<float4*>(ringW + 4 * l) = make_float4(0.f, 0.f, 0.f, 0.f);
        float2 x1o = make_float2(0.f, 0.f), x2o = make_float2(0.f, 0.f);
        __syncthreads();   // prologue barrier

        for (int B = 0; B <= nfull; ++B) {
            if (B < nfull) {
                if (B & 1)
                    produce8<8>(ringW, l, d0, d1, tf2, na2, mu22, x1o, x2o);
                else
                    produce8<0>(ringW, l, d0, d1, tf2, na2, mu22, x1o, x2o);
            } else if (rem) {
                produce_tail(ringW, l, d0, d1, tf2, na2, mu22, x1o, x2o,
                             8 * nfull + 1, rem);
            }
            __syncthreads();
        }
    } else {
        // -------- CONSUMER --------
        const int cw = wid - 4;
        const int r = blockIdx.x * 4 + cw;
        const float* ringW = ring + cw * 132;

        unsigned long long hreg[32];
#pragma unroll
        for (int m = 0; m < 16; ++m) {
            ulonglong2 hv = *reinterpret_cast<const ulonglong2*>(&Ht[m * 128 + 4 * l]);
            hreg[2 * m]     = hv.x;
            hreg[2 * m + 1] = hv.y;
        }

        float cl;
        {
            unsigned long long c0 = 0ull, c1 = 0ull, c2 = 0ull, c3 = 0ull;
#pragma unroll
            for (int m = 0; m < 8; ++m) {
                ulonglong2 bv0 = *reinterpret_cast<const ulonglong2*>(&bb[r * 64 + 8 * m]);
                ulonglong2 bv1 = *reinterpret_cast<const ulonglong2*>(&bb[r * 64 + 8 * m + 4]);
                c0 = ffma2(hreg[4 * m],     bv0.x, c0);
                c1 = ffma2(hreg[4 * m + 1], bv0.y, c1);
                c2 = ffma2(hreg[4 * m + 2], bv1.x, c2);
                c3 = ffma2(hreg[4 * m + 3], bv1.y, c3);
            }
            cl = hsum2(add2(add2(c0, c1), add2(c2, c3)));
        }

        float* xo = out + (size_t)r * K * 128;
        float* po = out + (size_t)BSZ * K * 128 + (size_t)r * K * 32;

        __stcs(reinterpret_cast<float4*>(&xo[4 * l]), make_float4(0.f, 0.f, 0.f, 0.f));
        __stcs(&po[l], -cl);
        __syncthreads();   // prologue barrier

        for (int B = 0; B <= nfull; ++B) {
            if (B > 0)
                consume_block(ringW, l, hreg, cl, xo, po, 8 * (B - 1) + 1, 8);
            __syncthreads();
        }
        if (rem)
            consume_block(ringW, l, hreg, cl, xo, po, 8 * nfull + 1, rem);
    }
}

// ----------------------------- launch -----------------------------
extern "C" void kernel_launch(void* const* d_in, const int* in_sizes, int n_in,
                              void* d_out, int out_size) {
    (void)in_sizes; (void)out_size;
    const float* q = (const float*)d_in[0];
    const float* b = (const float*)d_in[1];
    const float* P = (const float*)d_in[2];
    const float* H = (const float*)d_in[3];

    const int* itp;
    if (n_in >= 5) {
        itp = (const int*)d_in[4];
    } else {
        void* p = nullptr;
        cudaGetSymbolAddress(&p, gItersDefault);
        itp = (const int*)p;
    }
    float* out = (float*)d_out;

    static bool attr_set = false;
    if (!attr_set) {
        cudaFuncSetAttribute(qp_kernel, cudaFuncAttributeMaxDynamicSharedMemorySize, SMEM_BYTES);
        attr_set = true;
    }
    qp_kernel<<<128, 256, SMEM_BYTES>>>(itp, q, b, P, H, out);
}

// round 16
// speedup vs baseline: 1.4091x; 1.0610x over previous
#include <cuda_runtime.h>
#include <cstdint>

#define N32   32
#define M64   64
#define BSZ   512
#define ALPHA 1.0f
#define BETA  1.0f

__device__ int gItersDefault = 1000;

// Dynamic smem layout (floats):
//   ring [0:16896)       32 slots x 4 rows x 132
//   Dm   [16896:20992)   D (64x64)
//   Ht   [20992:23040)   Hinv tiles: Ht[m*128 + lane*4 + e] = Hinv[lane][4m+e]
// Preproc aliases inside ring region: w0 @0 (2048), w1 @2048 (1024), w2 @3072 (2048, E), sH @5120 (2048)
#define SMEM_FLOATS 23040
#define SMEM_BYTES  (SMEM_FLOATS * 4)

// ----------------------------- helpers -----------------------------
__device__ __forceinline__ unsigned long long ffma2(unsigned long long a,
                                                    unsigned long long b,
                                                    unsigned long long c) {
    unsigned long long d;
    asm("fma.rn.f32x2 %0, %1, %2, %3;" : "=l"(d) : "l"(a), "l"(b), "l"(c));
    return d;
}
__device__ __forceinline__ unsigned long long add2(unsigned long long a,
                                                   unsigned long long b) {
    unsigned long long d;
    asm("add.rn.f32x2 %0, %1, %2;" : "=l"(d) : "l"(a), "l"(b));
    return d;
}
__device__ __forceinline__ float hsum2(unsigned long long a) {
    float lo, hi;
    asm("mov.b64 {%0, %1}, %2;" : "=f"(lo), "=f"(hi) : "l"(a));
    return lo + hi;
}
// compiler-only ordering fence (branch-free converged warp; no WARPSYNC emitted)
__device__ __forceinline__ void cfence() { asm volatile("" ::: "memory"); }

__device__ __forceinline__ float warpMax(float v) {
#pragma unroll
    for (int o = 16; o; o >>= 1) v = fmaxf(v, __shfl_xor_sync(0xffffffffu, v, o));
    return v;
}
__device__ __forceinline__ float warpSum(float v) {
#pragma unroll
    for (int o = 16; o; o >>= 1) v += __shfl_xor_sync(0xffffffffu, v, o);
    return v;
}

// ----------------------------- producer: one 8-iter block, compile-time slots -----------------------------
template<int S0>
__device__ __forceinline__ void produce8(
    float* __restrict__ ringW, int l,
    const unsigned long long* __restrict__ d0,
    const unsigned long long* __restrict__ d1,
    float tf, float a2t, float c22, float2 mu2, float2 b2,
    float2& x1o, float2& x2o)
{
#pragma unroll
    for (int j = 0; j < 8; ++j) {
        const float* Xr = ringW + (S0 + j) * 528;
        unsigned long long a00 = 0ull, a01 = 0ull, a02 = 0ull, a03 = 0ull;
        unsigned long long a10 = 0ull, a11 = 0ull, a12 = 0ull, a13 = 0ull;
#pragma unroll
        for (int q4 = 0; q4 < 8; ++q4) {
            ulonglong2 xv = *reinterpret_cast<const ulonglong2*>(Xr + 4 * q4);
            a00 = ffma2(d0[2 * q4],     xv.x, a00);
            a01 = ffma2(d0[2 * q4 + 1], xv.y, a01);
            a10 = ffma2(d1[2 * q4],     xv.x, a10);
            a11 = ffma2(d1[2 * q4 + 1], xv.y, a11);
        }
#pragma unroll
        for (int q4 = 8; q4 < 16; ++q4) {
            ulonglong2 xv = *reinterpret_cast<const ulonglong2*>(Xr + 4 * q4);
            a02 = ffma2(d0[2 * q4],     xv.x, a02);
            a03 = ffma2(d0[2 * q4 + 1], xv.y, a03);
            a12 = ffma2(d1[2 * q4],     xv.x, a12);
            a13 = ffma2(d1[2 * q4 + 1], xv.y, a13);
        }
        float w0s = hsum2(add2(add2(a00, a01), add2(a02, a03)));
        float w1s = hsum2(add2(add2(a10, a11), add2(a12, a13)));

        float2 m1, m2;
        m1.x = fmaf(tf, w0s + x2o.x, mu2.x);
        m1.y = fmaf(tf, w1s + x2o.y, mu2.y);
        m2.x = fmaxf(fmaf(-a2t, w0s, fmaf(c22, x2o.x, x1o.x)) + b2.x, 0.0f);
        m2.y = fmaxf(fmaf(-a2t, w1s, fmaf(c22, x2o.y, x1o.y)) + b2.y, 0.0f);
        x1o = m1; x2o = m2;

        float* Xw = ringW + ((S0 + j + 1) & 31) * 528;
        *reinterpret_cast<float2*>(Xw + 2 * l)      = m1;
        *reinterpret_cast<float2*>(Xw + 64 + 2 * l) = m2;
        cfence();
    }
}

// runtime-slot tail producer (iters % 16 != 0 only)
__device__ __forceinline__ void produce_tail(
    float* __restrict__ ringW, int l,
    const unsigned long long* __restrict__ d0,
    const unsigned long long* __restrict__ d1,
    float tf, float a2t, float c22, float2 mu2, float2 b2,
    float2& x1o, float2& x2o, int kb, int nk)
{
    for (int j = 0; j < nk; ++j) {
        int k = kb + j;
        const float* Xr = ringW + ((k - 1) & 31) * 528;
        unsigned long long a00 = 0ull, a01 = 0ull, a10 = 0ull, a11 = 0ull;
#pragma unroll
        for (int q4 = 0; q4 < 16; ++q4) {
            ulonglong2 xv = *reinterpret_cast<const ulonglong2*>(Xr + 4 * q4);
            a00 = ffma2(d0[2 * q4],     xv.x, a00);
            a01 = ffma2(d0[2 * q4 + 1], xv.y, a01);
            a10 = ffma2(d1[2 * q4],     xv.x, a10);
            a11 = ffma2(d1[2 * q4 + 1], xv.y, a11);
        }
        float w0s = hsum2(add2(a00, a01));
        float w1s = hsum2(add2(a10, a11));
        float2 m1, m2;
        m1.x = fmaf(tf, w0s + x2o.x, mu2.x);
        m1.y = fmaf(tf, w1s + x2o.y, mu2.y);
        m2.x = fmaxf(fmaf(-a2t, w0s, fmaf(c22, x2o.x, x1o.x)) + b2.x, 0.0f);
        m2.y = fmaxf(fmaf(-a2t, w1s, fmaf(c22, x2o.y, x1o.y)) + b2.y, 0.0f);
        x1o = m1; x2o = m2;
        float* Xw = ringW + (k & 31) * 528;
        *reinterpret_cast<float2*>(Xw + 2 * l)      = m1;
        *reinterpret_cast<float2*>(Xw + 64 + 2 * l) = m2;
        cfence();
    }
}

// consumer: primal + gmem stores for nk iterations starting at kb
__device__ __forceinline__ void consume_block(
    const float* __restrict__ ringW, int l,
    const unsigned long long* __restrict__ hreg, float cl,
    float* __restrict__ xo, float* __restrict__ po,
    int kb, int nk)
{
    for (int j = 0; j < nk; ++j) {
        int k = kb + j;
        const float* xr = ringW + (k & 31) * 528;
        unsigned long long p0 = 0ull, p1 = 0ull, p2 = 0ull, p3 = 0ull;
#pragma unroll
        for (int m = 0; m < 8; ++m) {
            ulonglong2 x0 = *reinterpret_cast<const ulonglong2*>(xr + 64 + 8 * m);
            ulonglong2 x1 = *reinterpret_cast<const ulonglong2*>(xr + 64 + 8 * m + 4);
            p0 = ffma2(hreg[4 * m],     x0.x, p0);
            p1 = ffma2(hreg[4 * m + 1], x0.y, p1);
            p2 = ffma2(hreg[4 * m + 2], x1.x, p2);
            p3 = ffma2(hreg[4 * m + 3], x1.y, p3);
        }
        float pv = hsum2(add2(add2(p0, p1), add2(p2, p3))) - cl;
        float4 v = *reinterpret_cast<const float4*>(xr + 4 * l);
        __stcs(reinterpret_cast<float4*>(xo + (size_t)k * 128 + 4 * l), v);
        __stcs(po + (size_t)k * 32 + l, pv);
    }
}

__global__ void __launch_bounds__(256, 1)
qp_kernel(const int* __restrict__ itp,
          const float* __restrict__ q, const float* __restrict__ bb,
          const float* __restrict__ P, const float* __restrict__ Hg,
          float* __restrict__ out) {
    extern __shared__ __align__(16) float smem[];
    __shared__ float sred8[8];
    __shared__ float sy[64], sz[64];
    __shared__ float sTf;
    __shared__ int sidx;

    float* ring = smem;
    float* Dm   = smem + 16896;
    float* Ht   = smem + 20992;
    float* w0 = ring;
    float* w1 = ring + 2048;
    float* w2 = ring + 3072;
    float* sH = ring + 5120;

    const int tid = threadIdx.x;
    const int wid = tid >> 5;
    const int l   = tid & 31;

    for (int i = tid; i < 2048; i += 256) sH[i] = Hg[i];

    // ================= PHASE 1: preprocessing =================
    for (int i = tid; i < 2048; i += 256) {
        int r = i >> 6, c = i & 63;
        w0[i] = (c < 32) ? P[r * 32 + c] : ((c - 32 == r) ? 1.0f : 0.0f);
    }
    __syncthreads();
    for (int p = 0; p < 32; ++p) {
        float pv = w0[p * 64 + p];
        float ipv = 1.0f / pv;
        __syncthreads();
        if (tid < 64) w0[p * 64 + tid] *= ipv;
        __syncthreads();
        int rr = tid >> 3, cs = (tid & 7) * 8;
        float f = w0[rr * 64 + p];
        __syncthreads();
        if (rr != p) {
#pragma unroll
            for (int c = 0; c < 8; ++c)
                w0[rr * 64 + cs + c] = fmaf(-f, w0[p * 64 + cs + c], w0[rr * 64 + cs + c]);
        }
        __syncthreads();
    }
    for (int i = tid; i < 1024; i += 256) w1[i] = w0[(i >> 5) * 64 + 32 + (i & 31)];
    __syncthreads();

    for (int i = tid; i < 2048; i += 256) {
        int r = i >> 6, c = i & 63;
        float s = 0.0f;
#pragma unroll 8
        for (int k = 0; k < 32; ++k) s = fmaf(w1[r * 32 + k], sH[c * 32 + k], s);
        w2[i] = s;
    }
    __syncthreads();

    for (int i = tid; i < 4096; i += 256) {
        int a = i >> 6, c = i & 63;
        float s0 = 0.0f, s1 = 0.0f;
        for (int k = 0; k < 32; k += 2) {
            s0 = fmaf(sH[a * 32 + k],     w2[k * 64 + c],       s0);
            s1 = fmaf(sH[a * 32 + k + 1], w2[(k + 1) * 64 + c], s1);
        }
        Dm[i] = s0 + s1;
    }
    for (int i = tid; i < 1024; i += 256) {
        int r = i >> 5, c = i & 31;
        float s0 = 0.0f, s1 = 0.0f;
        for (int m = 0; m < 64; m += 2) {
            s0 = fmaf(w2[r * 64 + m],     sH[m * 32 + c],       s0);
            s1 = fmaf(w2[r * 64 + m + 1], sH[(m + 1) * 32 + c], s1);
        }
        w0[i] = s0 + s1;
    }
    __syncthreads();

    {
        float loc = 0.0f;
        for (int i = tid; i < 1024; i += 256) loc = fmaxf(loc, fabsf(w0[i]));
        loc = warpMax(loc);
        if (l == 0) sred8[wid] = loc;
        __syncthreads();
        float m = 0.0f;
#pragma unroll
        for (int j = 0; j < 8; ++j) m = fmaxf(m, sred8[j]);
        float inv = 1.0f / m;
        for (int i = tid; i < 1024; i += 256) w0[i] *= inv;
        __syncthreads();
    }
    {
        const int r4 = tid >> 3, c4 = (tid & 7) << 2;
        float* cur = w0;
        float* nxt = w0 + 1024;
        for (int s = 0; s < 13; ++s) {
            float acc[4] = {0, 0, 0, 0};
            for (int k = 0; k < 32; ++k) {
                float a = cur[r4 * 32 + k];
#pragma unroll
                for (int j = 0; j < 4; ++j)
                    acc[j] = fmaf(a, cur[k * 32 + c4 + j], acc[j]);
            }
            float loc = fmaxf(fmaxf(fabsf(acc[0]), fabsf(acc[1])),
                              fmaxf(fabsf(acc[2]), fabsf(acc[3])));
            loc = warpMax(loc);
            if (l == 0) sred8[wid] = loc;
            __syncthreads();
            float m = 0.0f;
#pragma unroll
            for (int j = 0; j < 8; ++j) m = fmaxf(m, sred8[j]);
            float inv = 1.0f / m;
#pragma unroll
            for (int j = 0; j < 4; ++j) nxt[r4 * 32 + c4 + j] = acc[j] * inv;
            __syncthreads();
            float* t = cur; cur = nxt; nxt = t;
        }
        if (tid < 32) {
            float s = 0.0f;
            for (int i = 0; i < 32; ++i) { float v = cur[i * 32 + tid]; s = fmaf(v, v, s); }
            sy[tid] = s;
        }
        __syncthreads();
        if (tid == 0) {
            int bj = 0; float bm = -1.0f;
            for (int j = 0; j < 32; ++j) if (sy[j] > bm) { bm = sy[j]; bj = j; }
            sidx = bj;
        }
        __syncthreads();
        if (tid < 64) {
            float s = 0.0f;
            for (int i = 0; i < 32; ++i) s = fmaf(sH[tid * 32 + i], cur[i * 32 + sidx], s);
            sy[tid] = s;
        }
        __syncthreads();
        if (tid < 64) {
            float s = 0.0f;
            for (int k = 0; k < 64; ++k) s = fmaf(Dm[tid * 64 + k], sy[k], s);
            sz[tid] = s;
        }
        __syncthreads();
        float p1 = (tid < 64) ? sy[tid] * sz[tid] : 0.0f;
        float p2 = (tid < 64) ? sy[tid] * sy[tid] : 0.0f;
        p1 = warpSum(p1);
        p2 = warpSum(p2);
        __syncthreads();
        if (l == 0) { sy[wid] = p1; sz[wid] = p2; }
        __syncthreads();
        if (tid == 0) {
            float num = 0.0f, den = 0.0f;
#pragma unroll
            for (int j = 0; j < 8; ++j) { num += sy[j]; den += sz[j]; }
            sTf = BETA * den / num;
        }
    }
    __syncthreads();

    for (int i = tid; i < 2048; i += 256) {
        int r = i >> 6, c = i & 63;
        if (c < 32) {
            float s0 = 0.0f, s1 = 0.0f;
            for (int m = 0; m < 64; m += 2) {
                s0 = fmaf(sH[m * 32 + r],       sH[m * 32 + c],       s0);
                s1 = fmaf(sH[(m + 1) * 32 + r], sH[(m + 1) * 32 + c], s1);
            }
            w0[i] = s0 + s1;
        } else {
            w0[i] = (c - 32 == r) ? 1.0f : 0.0f;
        }
    }
    __syncthreads();
    for (int p = 0; p < 32; ++p) {
        float pv = w0[p * 64 + p];
        float ipv = 1.0f / pv;
        __syncthreads();
        if (tid < 64) w0[p * 64 + tid] *= ipv;
        __syncthreads();
        int rr = tid >> 3, cs = (tid & 7) * 8;
        float f = w0[rr * 64 + p];
        __syncthreads();
        if (rr != p) {
#pragma unroll
            for (int c = 0; c < 8; ++c)
                w0[rr * 64 + cs + c] = fmaf(-f, w0[p * 64 + cs + c], w0[rr * 64 + cs + c]);
        }
        __syncthreads();
    }
    for (int i = tid; i < 1024; i += 256) w1[i] = w0[(i >> 5) * 64 + 32 + (i & 31)];
    __syncthreads();

    for (int i = tid; i < 2048; i += 256) {
        int r = i >> 6, c = i & 63;
        float s = 0.0f;
#pragma unroll 8
        for (int k = 0; k < 32; ++k) s = fmaf(w1[r * 32 + k], sH[c * 32 + k], s);
        Ht[(c >> 2) * 128 + r * 4 + (c & 3)] = s;
    }
    __syncthreads();

    // ================= PHASE 2: producer (wid<4) / consumer (wid>=4), 1 of each per SMSP =================
    // 32-slot ring, barrier every 16 iterations; consumer trails one 16-block.
    const int iters = *itp;
    const size_t K = (size_t)iters + 1;
    const int nfull = iters >> 4;       // full 16-iter blocks
    const int rem = iters & 15;

    if (wid < 4) {
        // -------- PRODUCER --------
        const int w = wid;
        const int r = blockIdx.x * 4 + w;
        float* ringW = ring + w * 132;

        unsigned long long d0[32], d1[32];
#pragma unroll
        for (int kk = 0; kk < 32; ++kk) {
            d0[kk] = *reinterpret_cast<const unsigned long long*>(&Dm[(2 * l)     * 64 + 2 * kk]);
            d1[kk] = *reinterpret_cast<const unsigned long long*>(&Dm[(2 * l + 1) * 64 + 2 * kk]);
        }

        const float tf  = sTf;
        const float a2t = 2.0f * ALPHA * tf;
        const float c22 = 1.0f - a2t;

        float2 mu2;
        {
            float s0 = 0.0f, s1 = 0.0f;
#pragma unroll 8
            for (int i = 0; i < 32; ++i) {
                float qi = q[r * 32 + i];
                float2 ev = *reinterpret_cast<const float2*>(&w2[i * 64 + 2 * l]);
                s0 = fmaf(qi, ev.x, s0);
                s1 = fmaf(qi, ev.y, s1);
            }
            float2 bv = *reinterpret_cast<const float2*>(&bb[r * 64 + 2 * l]);
            mu2.x = tf * (s0 - bv.x);
            mu2.y = tf * (s1 - bv.y);
        }
        const float2 b2 = make_float2(-2.0f * ALPHA * mu2.x, -2.0f * ALPHA * mu2.y);

        *reinterpret_cast<float4*>(ringW + 4 * l) = make_float4(0.f, 0.f, 0.f, 0.f);
        float2 x1o = make_float2(0.f, 0.f), x2o = make_float2(0.f, 0.f);
        __syncthreads();   // prologue barrier

        for (int B = 0; B <= nfull; ++B) {
            if (B < nfull) {
                if (B & 1) {
                    produce8<16>(ringW, l, d0, d1, tf, a2t, c22, mu2, b2, x1o, x2o);
                    produce8<24>(ringW, l, d0, d1, tf, a2t, c22, mu2, b2, x1o, x2o);
                } else {
                    produce8<0>(ringW, l, d0, d1, tf, a2t, c22, mu2, b2, x1o, x2o);
                    produce8<8>(ringW, l, d0, d1, tf, a2t, c22, mu2, b2, x1o, x2o);
                }
            } else if (rem) {
                produce_tail(ringW, l, d0, d1, tf, a2t, c22, mu2, b2, x1o, x2o,
                             16 * nfull + 1, rem);
            }
            __syncthreads();
        }
    } else {
        // -------- CONSUMER --------
        const int cw = wid - 4;
        const int r = blockIdx.x * 4 + cw;
        const float* ringW = ring + cw * 132;

        unsigned long long hreg[32];
#pragma unroll
        for (int m = 0; m < 16; ++m) {
            ulonglong2 hv = *reinterpret_cast<const ulonglong2*>(&Ht[m * 128 + 4 * l]);
            hreg[2 * m]     = hv.x;
            hreg[2 * m + 1] = hv.y;
        }

        float cl;
        {
            unsigned long long c0 = 0ull, c1 = 0ull, c2 = 0ull, c3 = 0ull;
#pragma unroll
            for (int m = 0; m < 8; ++m) {
                ulonglong2 bv0 = *reinterpret_cast<const ulonglong2*>(&bb[r * 64 + 8 * m]);
                ulonglong2 bv1 = *reinterpret_cast<const ulonglong2*>(&bb[r * 64 + 8 * m + 4]);
                c0 = ffma2(hreg[4 * m],     bv0.x, c0);
                c1 = ffma2(hreg[4 * m + 1], bv0.y, c1);
                c2 = ffma2(hreg[4 * m + 2], bv1.x, c2);
                c3 = ffma2(hreg[4 * m + 3], bv1.y, c3);
            }
            cl = hsum2(add2(add2(c0, c1), add2(c2, c3)));
        }

        float* xo = out + (size_t)r * K * 128;
        float* po = out + (size_t)BSZ * K * 128 + (size_t)r * K * 32;

        __stcs(reinterpret_cast<float4*>(&xo[4 * l]), make_float4(0.f, 0.f, 0.f, 0.f));
        __stcs(&po[l], -cl);
        __syncthreads();   // prologue barrier

        for (int B = 0; B <= nfull; ++B) {
            if (B > 0)
                consume_block(ringW, l, hreg, cl, xo, po, 16 * (B - 1) + 1, 16);
            __syncthreads();
        }
        if (rem)
            consume_block(ringW, l, hreg, cl, xo, po, 16 * nfull + 1, rem);
    }
}

// ----------------------------- launch -----------------------------
extern "C" void kernel_launch(void* const* d_in, const int* in_sizes, int n_in,
                              void* d_out, int out_size) {
    (void)in_sizes; (void)out_size;
    const float* q = (const float*)d_in[0];
    const float* b = (const float*)d_in[1];
    const float* P = (const float*)d_in[2];
    const float* H = (const float*)d_in[3];

    const int* itp;
    if (n_in >= 5) {
        itp = (const int*)d_in[4];
    } else {
        void* p = nullptr;
        cudaGetSymbolAddress(&p, gItersDefault);
        itp = (const int*)p;
    }
    float* out = (float*)d_out;

    static bool attr_set = false;
    if (!attr_set) {
        cudaFuncSetAttribute(qp_kernel, cudaFuncAttributeMaxDynamicSharedMemorySize, SMEM_BYTES);
        attr_set = true;
    }
    qp_kernel<<<128, 256, SMEM_BYTES>>>(itp, q, b, P, H, out);
}